// round 16
// baseline (speedup 1.0000x reference)
#include <cuda_runtime.h>
#include <cstdint>

#define N_NODES 40000
#define N_EDGES 640000
#define NPAD    40960

// Scratch (allocation-free rule: __device__ globals)
__device__ float g_sv[N_NODES * 128];    // lin1 out, quad: [node][lane]=(s,vx,vy,vz)
__device__ float g_acc[N_NODES * 256];   // aggregation, quad-interleaved
__device__ int   g_hist[NPAD];
__device__ int   g_start[NPAD];
__device__ int   g_cursor[NPAD];
__device__ int   g_bsum[40];
// SORTED edge data (dst-ascending)
__device__ int2   g_ssd[N_EDGES];        // (src, dst)
__device__ float4 g_sea[N_EDGES];        // edge_attr
__device__ float4 g_ses[N_EDGES * 2];    // edge_scalars

__device__ __forceinline__ float silu_n(float x) {
    return (x / (1.0f + __expf(-x))) * 1.6791767923989418f;
}
__device__ __forceinline__ unsigned long long pk(float a, float b) {
    unsigned long long r;
    asm("mov.b64 %0, {%1,%2};" : "=l"(r) : "f"(a), "f"(b));
    return r;
}
__device__ __forceinline__ void fma2(unsigned long long& d,
                                     unsigned long long a, unsigned long long b) {
    asm("fma.rn.f32x2 %0, %1, %2, %0;" : "+l"(d) : "l"(a), "l"(b));
}
__device__ __forceinline__ float2 unpk(unsigned long long v) {
    float2 r;
    asm("mov.b64 {%0,%1}, %2;" : "=f"(r.x), "=f"(r.y) : "l"(v));
    return r;
}
__device__ __forceinline__ void red4(float* p, float a, float b, float c, float d) {
    asm volatile("red.global.add.v4.f32 [%0], {%1,%2,%3,%4};"
                 :: "l"(p), "f"(a), "f"(b), "f"(c), "f"(d) : "memory");
}
__device__ __forceinline__ uint32_t tf32b(float x) {
    uint32_t r;
    asm("cvt.rna.tf32.f32 %0, %1;" : "=r"(r) : "f"(x));
    return r;
}
__device__ __forceinline__ void mma_tf32(float d[4], uint32_t a0, uint32_t a1,
                                         uint32_t a2, uint32_t a3,
                                         uint32_t b0, uint32_t b1) {
    asm volatile(
        "mma.sync.aligned.m16n8k8.row.col.f32.tf32.tf32.f32 "
        "{%0,%1,%2,%3}, {%4,%5,%6,%7}, {%8,%9}, {%0,%1,%2,%3};"
        : "+f"(d[0]), "+f"(d[1]), "+f"(d[2]), "+f"(d[3])
        : "r"(a0), "r"(a1), "r"(a2), "r"(a3), "r"(b0), "r"(b1));
}
__device__ __forceinline__ void cpasync16(uint32_t s, const void* g) {
    asm volatile("cp.async.ca.shared.global [%0], [%1], 16;" :: "r"(s), "l"(g));
}
__device__ __forceinline__ void cpcommit() {
    asm volatile("cp.async.commit_group;" ::: "memory");
}
__device__ __forceinline__ void cpwait0() {
    asm volatile("cp.async.wait_group 0;" ::: "memory");
}

// ---------------------------------------------------------------------------
// Binning pipeline (verified)
// ---------------------------------------------------------------------------
__global__ void prep_zero_kernel() {
    int i = blockIdx.x * blockDim.x + threadIdx.x;
    if (i < NPAD) { g_hist[i] = 0; g_cursor[i] = 0; }
}
__global__ void hist_kernel(const int* __restrict__ edst) {
    int e = blockIdx.x * blockDim.x + threadIdx.x;
    if (e < N_EDGES) atomicAdd(&g_hist[edst[e]], 1);
}
__global__ void scan1_kernel() {
    __shared__ int sh[1024];
    int tid = threadIdx.x;
    int i = blockIdx.x * 1024 + tid;
    int v = g_hist[i];
    sh[tid] = v;
    __syncthreads();
#pragma unroll
    for (int off = 1; off < 1024; off <<= 1) {
        int t = (tid >= off) ? sh[tid - off] : 0;
        __syncthreads();
        sh[tid] += t;
        __syncthreads();
    }
    g_start[i] = sh[tid] - v;
    if (tid == 1023) g_bsum[blockIdx.x] = sh[1023];
}
__global__ void scatter_kernel(const int*    __restrict__ esrc,
                               const int*    __restrict__ edst,
                               const float4* __restrict__ eattr,
                               const float4* __restrict__ escal) {
    __shared__ int sb[40];
    int tid = threadIdx.x;
    if (tid < 40) sb[tid] = g_bsum[tid];
    __syncthreads();
    if (tid == 0) {
        int s = 0;
#pragma unroll
        for (int b = 0; b < 40; b++) { int v = sb[b]; sb[b] = s; s += v; }
    }
    __syncthreads();
    int e = blockIdx.x * blockDim.x + tid;
    if (e < N_EDGES) {
        int d = edst[e];
        int pos = g_start[d] + sb[d >> 10] + atomicAdd(&g_cursor[d], 1);
        g_ssd[pos] = make_int2(esrc[e], d);
        g_sea[pos] = eattr[e];
        g_ses[pos * 2 + 0] = escal[e * 2 + 0];
        g_ses[pos * 2 + 1] = escal[e * 2 + 1];
    }
}

// ---------------------------------------------------------------------------
// K1: lin1 (+ zero g_acc) — quad output layout
// ---------------------------------------------------------------------------
__global__ void lin1_kernel(const float* __restrict__ ni,
                            const float* __restrict__ w1s,
                            const float* __restrict__ w1v) {
    __shared__ float sWs[1024], sWv[1024];
    __shared__ float srow[8][128];
    int tid = threadIdx.x;
    {
        float4 z = make_float4(0.f, 0.f, 0.f, 0.f);
        size_t base = (size_t)blockIdx.x * 512;
        ((float4*)g_acc)[base + tid]       = z;
        ((float4*)g_acc)[base + 256 + tid] = z;
    }
    const float sc = 0.17677669529663687f;
    for (int i = tid; i < 1024; i += 256) { sWs[i] = w1s[i] * sc; sWv[i] = w1v[i] * sc; }
    __syncthreads();

    int warp = tid >> 5, lane = tid & 31;
    int node = blockIdx.x * 8 + warp;
    ((float4*)srow[warp])[lane] = ((const float4*)(ni + (size_t)node * 128))[lane];
    __syncwarp();

    float s = 0.f, v0 = 0.f, v1 = 0.f, v2 = 0.f;
#pragma unroll
    for (int u = 0; u < 32; u++) {
        float su = srow[warp][u];
        float a0 = srow[warp][32 + u * 3 + 0];
        float a1 = srow[warp][32 + u * 3 + 1];
        float a2 = srow[warp][32 + u * 3 + 2];
        float ws = sWs[u * 32 + lane];
        float wv = sWv[u * 32 + lane];
        s  = fmaf(su, ws, s);
        v0 = fmaf(a0, wv, v0);
        v1 = fmaf(a1, wv, v1);
        v2 = fmaf(a2, wv, v2);
    }
    ((float4*)(g_sv + (size_t)node * 128))[lane] = make_float4(s, v0, v1, v2);
}

// ---------------------------------------------------------------------------
// K2 (FUSED): per warp-tile of 16 sorted edges. Same design as R15 with the
// cp.async SOURCE ADDRESS FIXED: tile t's escal lives at g_ses + t*32
// (float4 units), not t*2.
// ---------------------------------------------------------------------------
#define WST 136
#define WARP_SCRATCH (256 + 16 * WST)
#define EDGE_SMEM_FLOATS (8192 + 4 * WARP_SCRATCH)

__global__ void __launch_bounds__(128, 3)
edge_kernel(const float* __restrict__ fw1, const float* __restrict__ fw2) {
    extern __shared__ float smem[];
    float* Bf  = smem;                          // packed float4 B fragments
    int tid = threadIdx.x, lane = tid & 31, warp = tid >> 5;
    int gid = lane >> 2, qid = lane & 3;
    float* wsc = smem + 8192 + warp * WARP_SCRATCH;
    float* esc0 = wsc;          // escal buffer 0 (128 floats)
    float* esc1 = wsc + 128;    // escal buffer 1
    float* hw   = wsc + 256;    // tf32 h [16][68]
    float* wst  = wsc + 256;    // w stage (reuses hw region), 16*WST

    // build B fragment cache, float4-packed per (k-pair, nt, lane)
    for (int fi = tid; fi < 8192; fi += 128) {
        int sub    = fi & 3;
        int lane_f = (fi >> 2) & 31;
        int nt     = (fi >> 7) & 15;
        int kp     = fi >> 11;
        int k      = kp * 2 + (sub >> 1);
        int which  = sub & 1;
        int tf = lane_f & 3, gf = lane_f >> 2;
        int j = k * 8 + tf + which * 4;
        int n = nt * 8 + gf;
        int col = (n & 3) * 32 + (n >> 2);
        Bf[fi] = __uint_as_float(tf32b(fw2[j * 128 + col] * 0.125f));
    }
    float wA[8], wB[8];
#pragma unroll
    for (int i = 0; i < 8; i++) {
        wA[i] = fw1[i * 64 + lane]      * 0.3535533905932738f;
        wB[i] = fw1[i * 64 + 32 + lane] * 0.3535533905932738f;
    }
    __syncthreads();

    const int ntiles = N_EDGES / 16;
    const int nw = gridDim.x * 4;
    int t = blockIdx.x * 4 + warp;
    uint32_t s0 = (uint32_t)__cvta_generic_to_shared(esc0) + lane * 16;
    uint32_t s1 = (uint32_t)__cvta_generic_to_shared(esc1) + lane * 16;

    // preload first tile's escal (tile t -> g_ses + t*32 float4)
    if (t < ntiles) {
        cpasync16(s0, (const char*)(g_ses + (size_t)t * 32) + lane * 16);
        cpcommit();
    }
    float* cur = esc0; float* nxt = esc1;
    uint32_t scur = s0, snxt = s1;

    for (; t < ntiles; t += nw) {
        int e0 = t * 16;

        // prefetch src/dst and FIRST 8 gathers (independent of MLP)
        int2 sd[16];
#pragma unroll
        for (int e = 0; e < 16; e++) sd[e] = g_ssd[e0 + e];
        float4 qv[8];
#pragma unroll
        for (int e = 0; e < 8; e++)
            qv[e] = ((const float4*)(g_sv + (size_t)sd[e].x * 128))[lane];

        cpwait0();          // current escal buffer ready
        __syncwarp();

        // layer 1 (explicit LDS.128 pairs)
#pragma unroll 4
        for (int e = 0; e < 16; e++) {
            float4 xA = *(const float4*)(cur + e * 8);
            float4 xB = *(const float4*)(cur + e * 8 + 4);
            float a0, a1;
            a0 = xA.x * wA[0];            a1 = xA.x * wB[0];
            a0 = fmaf(xA.y, wA[1], a0);   a1 = fmaf(xA.y, wB[1], a1);
            a0 = fmaf(xA.z, wA[2], a0);   a1 = fmaf(xA.z, wB[2], a1);
            a0 = fmaf(xA.w, wA[3], a0);   a1 = fmaf(xA.w, wB[3], a1);
            a0 = fmaf(xB.x, wA[4], a0);   a1 = fmaf(xB.x, wB[4], a1);
            a0 = fmaf(xB.y, wA[5], a0);   a1 = fmaf(xB.y, wB[5], a1);
            a0 = fmaf(xB.z, wA[6], a0);   a1 = fmaf(xB.z, wB[6], a1);
            a0 = fmaf(xB.w, wA[7], a0);   a1 = fmaf(xB.w, wB[7], a1);
            hw[e * 68 + lane]      = __uint_as_float(tf32b(silu_n(a0)));
            hw[e * 68 + 32 + lane] = __uint_as_float(tf32b(silu_n(a1)));
        }
        __syncwarp();

        // issue next tile's escal prefetch (covered by MMA + Phase C)
        int tn = t + nw;
        if (tn < ntiles) {
            cpasync16(snxt, (const char*)(g_ses + (size_t)tn * 32) + lane * 16);
            cpcommit();
        }

        // MMA: D[16 edges x 128 packed outputs]; B loads as float4 per k-pair
        float d[16][4];
#pragma unroll
        for (int nt = 0; nt < 16; nt++)
            d[nt][0] = d[nt][1] = d[nt][2] = d[nt][3] = 0.f;
#pragma unroll
        for (int kp = 0; kp < 4; kp++) {
            int k0 = kp * 2, k1 = k0 + 1;
            uint32_t p0 = __float_as_uint(hw[gid * 68 + k0 * 8 + qid]);
            uint32_t p1 = __float_as_uint(hw[(gid + 8) * 68 + k0 * 8 + qid]);
            uint32_t p2 = __float_as_uint(hw[gid * 68 + k0 * 8 + qid + 4]);
            uint32_t p3 = __float_as_uint(hw[(gid + 8) * 68 + k0 * 8 + qid + 4]);
            uint32_t r0 = __float_as_uint(hw[gid * 68 + k1 * 8 + qid]);
            uint32_t r1 = __float_as_uint(hw[(gid + 8) * 68 + k1 * 8 + qid]);
            uint32_t r2 = __float_as_uint(hw[gid * 68 + k1 * 8 + qid + 4]);
            uint32_t r3 = __float_as_uint(hw[(gid + 8) * 68 + k1 * 8 + qid + 4]);
#pragma unroll
            for (int nt = 0; nt < 16; nt++) {
                float4 b = ((const float4*)Bf)[(kp * 16 + nt) * 32 + lane];
                mma_tf32(d[nt], p0, p1, p2, p3,
                         __float_as_uint(b.x), __float_as_uint(b.y));
                mma_tf32(d[nt], r0, r1, r2, r3,
                         __float_as_uint(b.z), __float_as_uint(b.w));
            }
        }
        __syncwarp();   // hw dead; reuse as w stage

        // prefetch SECOND 8 gathers
        float4 qv2[8];
#pragma unroll
        for (int e = 0; e < 8; e++)
            qv2[e] = ((const float4*)(g_sv + (size_t)sd[8 + e].x * 128))[lane];

        // stage w to smem
#pragma unroll
        for (int nt = 0; nt < 16; nt++) {
            *(float2*)(wst + (size_t)gid * WST + nt * 8 + qid * 2)
                = make_float2(d[nt][0], d[nt][1]);
            *(float2*)(wst + (size_t)(gid + 8) * WST + nt * 8 + qid * 2)
                = make_float2(d[nt][2], d[nt][3]);
        }
        __syncwarp();

        // Phase C: tensor product + dst-run register accumulation
        int curd = sd[0].y;
        float A0 = 0.f, A1 = 0.f, A2 = 0.f, A3 = 0.f;
        float B0 = 0.f, B1 = 0.f, B2 = 0.f, B3 = 0.f;
#pragma unroll
        for (int e = 0; e < 16; e++) {
            if (sd[e].y != curd) {   // warp-uniform
                float* ar = g_acc + (size_t)curd * 256;
                red4(ar + lane * 4,       A0, A1, A2, A3);
                red4(ar + 128 + lane * 4, B0, B1, B2, B3);
                A0 = A1 = A2 = A3 = B0 = B1 = B2 = B3 = 0.f;
                curd = sd[e].y;
            }
            float4 ea = g_sea[e0 + e];
            float4 q  = (e < 8) ? qv[e & 7] : qv2[e & 7];
            float4 wq = *(const float4*)(wst + e * WST + lane * 4);
            float se = q.x, vx = q.y, vy = q.z, vz = q.w;
            float dotv = fmaf(vx, ea.y, fmaf(vy, ea.z, vz * ea.w));
            float ms0 = wq.x * se * ea.x;
            float ms1 = wq.w * dotv * 0.5773502691896258f;
            float aa  = wq.y * se;
            float bb  = wq.z * ea.x;
            A0 += ms0; A1 += aa * ea.y; A2 += aa * ea.z; A3 += aa * ea.w;
            B0 += ms1; B1 += bb * vx;   B2 += bb * vy;   B3 += bb * vz;
        }
        {
            float* ar = g_acc + (size_t)curd * 256;
            red4(ar + lane * 4,       A0, A1, A2, A3);
            red4(ar + 128 + lane * 4, B0, B1, B2, B3);
        }
        __syncwarp();

        // swap escal buffers
        float* tp = cur; cur = nxt; nxt = tp;
        uint32_t ts = scur; scur = snxt; snxt = ts;
    }
}

// ---------------------------------------------------------------------------
// K3: lin2 — two nodes per warp (weight LDS amortized). Block 256, grid N/16.
// ---------------------------------------------------------------------------
__global__ void __launch_bounds__(256, 2)
lin2_kernel(const float* __restrict__ w2s,
            const float* __restrict__ w2v,
            float* __restrict__ out) {
    __shared__ float sW[4096];          // (ws,wv) pairs: [u][lane][2]
    __shared__ float srow[16][256];     // 16 node rows, quad-interleaved
    int tid = threadIdx.x;
    const float sc = 0.03125f;
    for (int i = tid; i < 2048; i += 256) {
        sW[i * 2 + 0] = w2s[i] * sc;
        sW[i * 2 + 1] = w2v[i] * sc;
    }
    int node0 = blockIdx.x * 16;
#pragma unroll
    for (int r = 0; r < 4; r++)
        ((float4*)srow)[tid + r * 256] =
            ((const float4*)(g_acc + (size_t)node0 * 256))[tid + r * 256];
    __syncthreads();

    int warp = tid >> 5, lane = tid & 31;
    int nA = warp * 2, nB = warp * 2 + 1;

    unsigned long long accA0 = 0ull, accA1 = 0ull;
    unsigned long long accB0 = 0ull, accB1 = 0ull;
#pragma unroll 8
    for (int u = 0; u < 64; u++) {
        float2 wsv = ((const float2*)sW)[u * 32 + lane];
        unsigned long long wp = pk(wsv.x, wsv.y);
        unsigned long long wv2 = pk(wsv.y, wsv.y);
        float4 qA = ((const float4*)srow[nA])[u];
        float4 qB = ((const float4*)srow[nB])[u];
        fma2(accA0, pk(qA.x, qA.y), wp);
        fma2(accA1, pk(qA.z, qA.w), wv2);
        fma2(accB0, pk(qB.x, qB.y), wp);
        fma2(accB1, pk(qB.z, qB.w), wv2);
    }
    float2 rA0 = unpk(accA0), rA1 = unpk(accA1);
    float2 rB0 = unpk(accB0), rB1 = unpk(accB1);
    float* oA = out + (size_t)(node0 + nA) * 128;
    oA[lane] = rA0.x;
    oA[32 + lane * 3 + 0] = rA0.y;
    oA[32 + lane * 3 + 1] = rA1.x;
    oA[32 + lane * 3 + 2] = rA1.y;
    float* oB = out + (size_t)(node0 + nB) * 128;
    oB[lane] = rB0.x;
    oB[32 + lane * 3 + 0] = rB0.y;
    oB[32 + lane * 3 + 1] = rB1.x;
    oB[32 + lane * 3 + 2] = rB1.y;
}

// ---------------------------------------------------------------------------
extern "C" void kernel_launch(void* const* d_in, const int* in_sizes, int n_in,
                              void* d_out, int out_size) {
    const float* node_input = (const float*)d_in[0];
    const int*   esrc  = (const int*)d_in[2];
    const int*   edst  = (const int*)d_in[3];
    const float* eattr = (const float*)d_in[4];
    const float* escal = (const float*)d_in[5];
    const float* w1s   = (const float*)d_in[6];
    const float* w1v   = (const float*)d_in[7];
    const float* fw1   = (const float*)d_in[8];
    const float* fw2   = (const float*)d_in[9];
    const float* w2s   = (const float*)d_in[10];
    const float* w2v   = (const float*)d_in[11];
    float* out = (float*)d_out;

    static bool attr_set = false;
    if (!attr_set) {
        cudaFuncSetAttribute(edge_kernel,
                             cudaFuncAttributeMaxDynamicSharedMemorySize,
                             EDGE_SMEM_FLOATS * 4);
        attr_set = true;
    }

    prep_zero_kernel<<<(NPAD + 255) / 256, 256>>>();
    hist_kernel<<<(N_EDGES + 255) / 256, 256>>>(edst);
    scan1_kernel<<<40, 1024>>>();
    scatter_kernel<<<(N_EDGES + 255) / 256, 256>>>(esrc, edst,
                                                   (const float4*)eattr,
                                                   (const float4*)escal);
    lin1_kernel<<<N_NODES / 8, 256>>>(node_input, w1s, w1v);
    edge_kernel<<<444, 128, EDGE_SMEM_FLOATS * 4>>>(fw1, fw2);
    lin2_kernel<<<N_NODES / 16, 256>>>(w2s, w2v, out);
}

// round 17
// speedup vs baseline: 1.0849x; 1.0849x over previous
#include <cuda_runtime.h>
#include <cstdint>

#define N_NODES 40000
#define N_EDGES 640000
#define NPAD    40960

// Scratch (allocation-free rule: __device__ globals)
__device__ float g_sv[N_NODES * 128];    // lin1 out, quad: [node][lane]=(s,vx,vy,vz)
__device__ float g_acc[N_NODES * 256];   // aggregation, quad-interleaved
__device__ int   g_hist[NPAD];
__device__ int   g_start[NPAD];
__device__ int   g_cursor[NPAD];
__device__ int   g_bsum[40];
// SORTED edge data (dst-ascending)
__device__ int2   g_ssd[N_EDGES];        // (src, dst)
__device__ float4 g_sea[N_EDGES];        // edge_attr
__device__ float4 g_ses[N_EDGES * 2];    // edge_scalars

__device__ __forceinline__ float silu_n(float x) {
    return (x / (1.0f + __expf(-x))) * 1.6791767923989418f;
}
__device__ __forceinline__ unsigned long long pk(float a, float b) {
    unsigned long long r;
    asm("mov.b64 %0, {%1,%2};" : "=l"(r) : "f"(a), "f"(b));
    return r;
}
__device__ __forceinline__ void fma2(unsigned long long& d,
                                     unsigned long long a, unsigned long long b) {
    asm("fma.rn.f32x2 %0, %1, %2, %0;" : "+l"(d) : "l"(a), "l"(b));
}
__device__ __forceinline__ float2 unpk(unsigned long long v) {
    float2 r;
    asm("mov.b64 {%0,%1}, %2;" : "=f"(r.x), "=f"(r.y) : "l"(v));
    return r;
}
__device__ __forceinline__ void red4(float* p, float a, float b, float c, float d) {
    asm volatile("red.global.add.v4.f32 [%0], {%1,%2,%3,%4};"
                 :: "l"(p), "f"(a), "f"(b), "f"(c), "f"(d) : "memory");
}
__device__ __forceinline__ uint32_t tf32b(float x) {
    uint32_t r;
    asm("cvt.rna.tf32.f32 %0, %1;" : "=r"(r) : "f"(x));
    return r;
}
__device__ __forceinline__ void mma_tf32(float d[4], uint32_t a0, uint32_t a1,
                                         uint32_t a2, uint32_t a3,
                                         uint32_t b0, uint32_t b1) {
    asm volatile(
        "mma.sync.aligned.m16n8k8.row.col.f32.tf32.tf32.f32 "
        "{%0,%1,%2,%3}, {%4,%5,%6,%7}, {%8,%9}, {%0,%1,%2,%3};"
        : "+f"(d[0]), "+f"(d[1]), "+f"(d[2]), "+f"(d[3])
        : "r"(a0), "r"(a1), "r"(a2), "r"(a3), "r"(b0), "r"(b1));
}

// ---------------------------------------------------------------------------
// Binning pipeline (verified)
// ---------------------------------------------------------------------------
__global__ void prep_zero_kernel() {
    int i = blockIdx.x * blockDim.x + threadIdx.x;
    if (i < NPAD) { g_hist[i] = 0; g_cursor[i] = 0; }
}
__global__ void hist_kernel(const int* __restrict__ edst) {
    int e = blockIdx.x * blockDim.x + threadIdx.x;
    if (e < N_EDGES) atomicAdd(&g_hist[edst[e]], 1);
}
__global__ void scan1_kernel() {
    __shared__ int sh[1024];
    int tid = threadIdx.x;
    int i = blockIdx.x * 1024 + tid;
    int v = g_hist[i];
    sh[tid] = v;
    __syncthreads();
#pragma unroll
    for (int off = 1; off < 1024; off <<= 1) {
        int t = (tid >= off) ? sh[tid - off] : 0;
        __syncthreads();
        sh[tid] += t;
        __syncthreads();
    }
    g_start[i] = sh[tid] - v;
    if (tid == 1023) g_bsum[blockIdx.x] = sh[1023];
}
__global__ void scatter_kernel(const int*    __restrict__ esrc,
                               const int*    __restrict__ edst,
                               const float4* __restrict__ eattr,
                               const float4* __restrict__ escal) {
    __shared__ int sb[40];
    int tid = threadIdx.x;
    if (tid < 40) sb[tid] = g_bsum[tid];
    __syncthreads();
    if (tid == 0) {
        int s = 0;
#pragma unroll
        for (int b = 0; b < 40; b++) { int v = sb[b]; sb[b] = s; s += v; }
    }
    __syncthreads();
    int e = blockIdx.x * blockDim.x + tid;
    if (e < N_EDGES) {
        int d = edst[e];
        int pos = g_start[d] + sb[d >> 10] + atomicAdd(&g_cursor[d], 1);
        g_ssd[pos] = make_int2(esrc[e], d);
        g_sea[pos] = eattr[e];
        g_ses[pos * 2 + 0] = escal[e * 2 + 0];
        g_ses[pos * 2 + 1] = escal[e * 2 + 1];
    }
}

// ---------------------------------------------------------------------------
// K1: lin1 (+ zero g_acc) — quad output layout
// ---------------------------------------------------------------------------
__global__ void lin1_kernel(const float* __restrict__ ni,
                            const float* __restrict__ w1s,
                            const float* __restrict__ w1v) {
    __shared__ float sWs[1024], sWv[1024];
    __shared__ float srow[8][128];
    int tid = threadIdx.x;
    {
        float4 z = make_float4(0.f, 0.f, 0.f, 0.f);
        size_t base = (size_t)blockIdx.x * 512;
        ((float4*)g_acc)[base + tid]       = z;
        ((float4*)g_acc)[base + 256 + tid] = z;
    }
    const float sc = 0.17677669529663687f;
    for (int i = tid; i < 1024; i += 256) { sWs[i] = w1s[i] * sc; sWv[i] = w1v[i] * sc; }
    __syncthreads();

    int warp = tid >> 5, lane = tid & 31;
    int node = blockIdx.x * 8 + warp;
    ((float4*)srow[warp])[lane] = ((const float4*)(ni + (size_t)node * 128))[lane];
    __syncwarp();

    float s = 0.f, v0 = 0.f, v1 = 0.f, v2 = 0.f;
#pragma unroll
    for (int u = 0; u < 32; u++) {
        float su = srow[warp][u];
        float a0 = srow[warp][32 + u * 3 + 0];
        float a1 = srow[warp][32 + u * 3 + 1];
        float a2 = srow[warp][32 + u * 3 + 2];
        float ws = sWs[u * 32 + lane];
        float wv = sWv[u * 32 + lane];
        s  = fmaf(su, ws, s);
        v0 = fmaf(a0, wv, v0);
        v1 = fmaf(a1, wv, v1);
        v2 = fmaf(a2, wv, v2);
    }
    ((float4*)(g_sv + (size_t)node * 128))[lane] = make_float4(s, v0, v1, v2);
}

// ---------------------------------------------------------------------------
// K2 (FUSED): EXACT R14 version (measured best). Per warp-tile of 16 sorted
// edges: layer-1 scalar -> tf32 h in smem -> m16n8k8 MMAs -> w staged to smem
// -> Phase C gather (prefetched 8+8) + tensor product + dst-run RED flush.
// ---------------------------------------------------------------------------
#define WST 136
#define EDGE_SMEM_FLOATS (8192 + 4 * (16 * WST))

__global__ void __launch_bounds__(128, 3)
edge_kernel(const float* __restrict__ fw1, const float* __restrict__ fw2) {
    extern __shared__ float smem[];
    float* Bf  = smem;                          // [k][nt][lane][2] tf32 B fragments
    int tid = threadIdx.x, lane = tid & 31, warp = tid >> 5;
    int gid = lane >> 2, qid = lane & 3;
    float* wsc = smem + 8192 + warp * (16 * WST);

    for (int idx = tid; idx < 8192; idx += 128) {
        int which = idx & 1;
        int lf    = (idx >> 1) & 31;
        int nt    = (idx >> 6) & 15;
        int k     = idx >> 10;
        int tf    = lf & 3, gf = lf >> 2;
        int j = k * 8 + tf + which * 4;
        int n = nt * 8 + gf;
        int col = (n & 3) * 32 + (n >> 2);
        Bf[idx] = __uint_as_float(tf32b(fw2[j * 128 + col] * 0.125f));
    }
    float wA[8], wB[8];
#pragma unroll
    for (int i = 0; i < 8; i++) {
        wA[i] = fw1[i * 64 + lane]      * 0.3535533905932738f;
        wB[i] = fw1[i * 64 + 32 + lane] * 0.3535533905932738f;
    }
    __syncthreads();

    const int ntiles = N_EDGES / 16;
    for (int t = blockIdx.x * 4 + warp; t < ntiles; t += gridDim.x * 4) {
        int e0 = t * 16;
        float* scw = wsc;          // escal stage [16][8]
        float* hw  = wsc + 128;    // tf32 h [16][68]

        // prefetch src/dst and FIRST 8 gathers (independent of MLP)
        int2 sd[16];
#pragma unroll
        for (int e = 0; e < 16; e++) sd[e] = g_ssd[e0 + e];
        float4 qv[8];
#pragma unroll
        for (int e = 0; e < 8; e++)
            qv[e] = ((const float4*)(g_sv + (size_t)sd[e].x * 128))[lane];

        // stage escal, layer 1
        ((float4*)scw)[lane] = g_ses[(size_t)e0 * 2 + lane];
        __syncwarp();
#pragma unroll 4
        for (int e = 0; e < 16; e++) {
            const float* s8 = scw + e * 8;
            float a0 = 0.f, a1 = 0.f;
#pragma unroll
            for (int i = 0; i < 8; i++) {
                a0 = fmaf(s8[i], wA[i], a0);
                a1 = fmaf(s8[i], wB[i], a1);
            }
            hw[e * 68 + lane]      = __uint_as_float(tf32b(silu_n(a0)));
            hw[e * 68 + 32 + lane] = __uint_as_float(tf32b(silu_n(a1)));
        }
        __syncwarp();

        // MMA: D[16 edges x 128 packed outputs]
        float d[16][4];
#pragma unroll
        for (int nt = 0; nt < 16; nt++)
            d[nt][0] = d[nt][1] = d[nt][2] = d[nt][3] = 0.f;
#pragma unroll
        for (int k = 0; k < 8; k++) {
            uint32_t a0 = __float_as_uint(hw[gid * 68 + k * 8 + qid]);
            uint32_t a1 = __float_as_uint(hw[(gid + 8) * 68 + k * 8 + qid]);
            uint32_t a2 = __float_as_uint(hw[gid * 68 + k * 8 + qid + 4]);
            uint32_t a3 = __float_as_uint(hw[(gid + 8) * 68 + k * 8 + qid + 4]);
#pragma unroll
            for (int nt = 0; nt < 16; nt++) {
                float2 b = *(const float2*)(Bf + ((k * 16 + nt) * 32 + lane) * 2);
                mma_tf32(d[nt], a0, a1, a2, a3,
                         __float_as_uint(b.x), __float_as_uint(b.y));
            }
        }
        __syncwarp();   // hw dead; reuse scratch as w stage

        // prefetch SECOND 8 gathers
        float4 qv2[8];
#pragma unroll
        for (int e = 0; e < 8; e++)
            qv2[e] = ((const float4*)(g_sv + (size_t)sd[8 + e].x * 128))[lane];

        // stage w to smem
        float* wst = wsc;
#pragma unroll
        for (int nt = 0; nt < 16; nt++) {
            *(float2*)(wst + (size_t)gid * WST + nt * 8 + qid * 2)
                = make_float2(d[nt][0], d[nt][1]);
            *(float2*)(wst + (size_t)(gid + 8) * WST + nt * 8 + qid * 2)
                = make_float2(d[nt][2], d[nt][3]);
        }
        __syncwarp();

        // Phase C: tensor product + dst-run register accumulation
        int cur = sd[0].y;
        float A0 = 0.f, A1 = 0.f, A2 = 0.f, A3 = 0.f;
        float B0 = 0.f, B1 = 0.f, B2 = 0.f, B3 = 0.f;
#pragma unroll
        for (int e = 0; e < 16; e++) {
            if (sd[e].y != cur) {   // warp-uniform
                float* ar = g_acc + (size_t)cur * 256;
                red4(ar + lane * 4,       A0, A1, A2, A3);
                red4(ar + 128 + lane * 4, B0, B1, B2, B3);
                A0 = A1 = A2 = A3 = B0 = B1 = B2 = B3 = 0.f;
                cur = sd[e].y;
            }
            float4 ea = g_sea[e0 + e];
            float4 q  = (e < 8) ? qv[e & 7] : qv2[e & 7];
            float4 wq = *(const float4*)(wst + e * WST + lane * 4);
            float se = q.x, vx = q.y, vy = q.z, vz = q.w;
            float dotv = fmaf(vx, ea.y, fmaf(vy, ea.z, vz * ea.w));
            float ms0 = wq.x * se * ea.x;
            float ms1 = wq.w * dotv * 0.5773502691896258f;
            float aa  = wq.y * se;
            float bb  = wq.z * ea.x;
            A0 += ms0; A1 += aa * ea.y; A2 += aa * ea.z; A3 += aa * ea.w;
            B0 += ms1; B1 += bb * vx;   B2 += bb * vy;   B3 += bb * vz;
        }
        {
            float* ar = g_acc + (size_t)cur * 256;
            red4(ar + lane * 4,       A0, A1, A2, A3);
            red4(ar + 128 + lane * 4, B0, B1, B2, B3);
        }
        __syncwarp();
    }
}

// ---------------------------------------------------------------------------
// K3: lin2 — two nodes per warp (weight LDS amortized). Block 256, grid N/16.
// ---------------------------------------------------------------------------
__global__ void __launch_bounds__(256, 2)
lin2_kernel(const float* __restrict__ w2s,
            const float* __restrict__ w2v,
            float* __restrict__ out) {
    __shared__ float sW[4096];          // (ws,wv) pairs: [u][lane][2]
    __shared__ float srow[16][256];     // 16 node rows, quad-interleaved
    int tid = threadIdx.x;
    const float sc = 0.03125f;
    for (int i = tid; i < 2048; i += 256) {
        sW[i * 2 + 0] = w2s[i] * sc;
        sW[i * 2 + 1] = w2v[i] * sc;
    }
    int node0 = blockIdx.x * 16;
#pragma unroll
    for (int r = 0; r < 4; r++)
        ((float4*)srow)[tid + r * 256] =
            ((const float4*)(g_acc + (size_t)node0 * 256))[tid + r * 256];
    __syncthreads();

    int warp = tid >> 5, lane = tid & 31;
    int nA = warp * 2, nB = warp * 2 + 1;

    unsigned long long accA0 = 0ull, accA1 = 0ull;
    unsigned long long accB0 = 0ull, accB1 = 0ull;
#pragma unroll 8
    for (int u = 0; u < 64; u++) {
        float2 wsv = ((const float2*)sW)[u * 32 + lane];
        unsigned long long wp = pk(wsv.x, wsv.y);
        unsigned long long wv2 = pk(wsv.y, wsv.y);
        float4 qA = ((const float4*)srow[nA])[u];
        float4 qB = ((const float4*)srow[nB])[u];
        fma2(accA0, pk(qA.x, qA.y), wp);
        fma2(accA1, pk(qA.z, qA.w), wv2);
        fma2(accB0, pk(qB.x, qB.y), wp);
        fma2(accB1, pk(qB.z, qB.w), wv2);
    }
    float2 rA0 = unpk(accA0), rA1 = unpk(accA1);
    float2 rB0 = unpk(accB0), rB1 = unpk(accB1);
    float* oA = out + (size_t)(node0 + nA) * 128;
    oA[lane] = rA0.x;
    oA[32 + lane * 3 + 0] = rA0.y;
    oA[32 + lane * 3 + 1] = rA1.x;
    oA[32 + lane * 3 + 2] = rA1.y;
    float* oB = out + (size_t)(node0 + nB) * 128;
    oB[lane] = rB0.x;
    oB[32 + lane * 3 + 0] = rB0.y;
    oB[32 + lane * 3 + 1] = rB1.x;
    oB[32 + lane * 3 + 2] = rB1.y;
}

// ---------------------------------------------------------------------------
extern "C" void kernel_launch(void* const* d_in, const int* in_sizes, int n_in,
                              void* d_out, int out_size) {
    const float* node_input = (const float*)d_in[0];
    const int*   esrc  = (const int*)d_in[2];
    const int*   edst  = (const int*)d_in[3];
    const float* eattr = (const float*)d_in[4];
    const float* escal = (const float*)d_in[5];
    const float* w1s   = (const float*)d_in[6];
    const float* w1v   = (const float*)d_in[7];
    const float* fw1   = (const float*)d_in[8];
    const float* fw2   = (const float*)d_in[9];
    const float* w2s   = (const float*)d_in[10];
    const float* w2v   = (const float*)d_in[11];
    float* out = (float*)d_out;

    static bool attr_set = false;
    if (!attr_set) {
        cudaFuncSetAttribute(edge_kernel,
                             cudaFuncAttributeMaxDynamicSharedMemorySize,
                             EDGE_SMEM_FLOATS * 4);
        attr_set = true;
    }

    prep_zero_kernel<<<(NPAD + 255) / 256, 256>>>();
    hist_kernel<<<(N_EDGES + 255) / 256, 256>>>(edst);
    scan1_kernel<<<40, 1024>>>();
    scatter_kernel<<<(N_EDGES + 255) / 256, 256>>>(esrc, edst,
                                                   (const float4*)eattr,
                                                   (const float4*)escal);
    lin1_kernel<<<N_NODES / 8, 256>>>(node_input, w1s, w1v);
    edge_kernel<<<444, 128, EDGE_SMEM_FLOATS * 4>>>(fw1, fw2);
    lin2_kernel<<<N_NODES / 16, 256>>>(w2s, w2v, out);
}